// round 9
// baseline (speedup 1.0000x reference)
#include <cuda_runtime.h>

#define B_DIM 256
#define T_DIM 64
#define D_DIM 2048
#define THRESHOLD 0.99f
#define EPSILON 0.01f

#define THREADS 128
#define D4 (D_DIM / 4)                    // 512 float4 per row
#define BLOCKS_PER_B 2                    // 2 chunks of 256 float4 columns
#define COLS_PER_THREAD 2
#define PF 4                              // prefetch depth (covers h<=3: ~96%)

// ---------------------------------------------------------------------------
// Sparse ACT kernel, barrier-free, 2 columns/thread.
// weights[t]==0 for t>h and h~2 for U(0,1) halt probs -> only rows t<=h
// matter. Each warp redundantly computes halting weights via shuffle scan
// (no smem, no __syncthreads), overlapped with an 8-load row prefetch
// (4 t-steps x 2 columns). grid = B*2, block = 128.
// ---------------------------------------------------------------------------
__global__ __launch_bounds__(THREADS)
void act_sparse_kernel(const float* __restrict__ halt_probs,   // [B,T]
                       const float* __restrict__ outputs,      // [B,T,D]
                       const float* __restrict__ step_weights, // [B,T]
                       float* __restrict__ final_out,          // [B,D]
                       float* __restrict__ out_ponder,         // [B]
                       float* __restrict__ out_weights)        // [B,T]
{
    const int b     = blockIdx.x / BLOCKS_PER_B;
    const int chunk = blockIdx.x % BLOCKS_PER_B;
    const int tid   = threadIdx.x;
    const int warp  = tid >> 5;
    const int lane  = tid & 31;
    const unsigned FULL = 0xFFFFFFFFu;

    // two coalesced columns per thread, 128 apart
    const int d4a = chunk * (THREADS * COLS_PER_THREAD) + tid;   // [0, D4)
    const int d4b = d4a + THREADS;

    const float4* __restrict__ basea =
        reinterpret_cast<const float4*>(outputs) + (size_t)b * T_DIM * D4 + d4a;
    const float4* __restrict__ baseb =
        reinterpret_cast<const float4*>(outputs) + (size_t)b * T_DIM * D4 + d4b;

    // ---- issue 8 independent row prefetches FIRST ----
    float4 a0 = __ldcs(basea + 0 * D4);
    float4 b0 = __ldcs(baseb + 0 * D4);
    float4 a1 = __ldcs(basea + 1 * D4);
    float4 b1 = __ldcs(baseb + 1 * D4);
    float4 a2 = __ldcs(basea + 2 * D4);
    float4 b2 = __ldcs(baseb + 2 * D4);
    float4 a3 = __ldcs(basea + 3 * D4);
    float4 b3 = __ldcs(baseb + 3 * D4);

    // ---- per-warp redundant weight computation (overlaps row loads) ----
    // lane owns t = 2*lane, 2*lane+1
    const float2 p  = reinterpret_cast<const float2*>(halt_probs   + b * T_DIM)[lane];
    const float2 sw = reinterpret_cast<const float2*>(step_weights + b * T_DIM)[lane];

    const float pairsum = p.x + p.y;
    float s = pairsum;
    #pragma unroll
    for (int o = 1; o < 32; o <<= 1) {
        float n = __shfl_up_sync(FULL, s, o);
        if (lane >= o) s += n;
    }
    const float excl = s - pairsum;
    const float cum0 = excl + p.x;
    const float cum1 = s;

    const unsigned m0 = __ballot_sync(FULL, cum0 >= THRESHOLD);
    const unsigned m1 = __ballot_sync(FULL, cum1 >= THRESHOLD);
    const int c0 = m0 ? 2 * (__ffs(m0) - 1)     : T_DIM;
    const int c1 = m1 ? 2 * (__ffs(m1) - 1) + 1 : T_DIM;
    int h = min(c0, c1);
    if (h >= T_DIM) h = T_DIM - 1;

    const int   hl   = h >> 1;
    const int   hodd = h & 1;
    const float cum_at = __shfl_sync(FULL, hodd ? cum1 : cum0, hl);
    const float p_at   = __shfl_sync(FULL, hodd ? p.y  : p.x,  hl);
    const float rem    = 1.0f - cum_at + p_at;

    const int t0i = 2 * lane, t1i = 2 * lane + 1;
    float w0 = (t0i < h) ? p.x : ((t0i == h) ? rem : 0.0f);
    float w1 = (t1i < h) ? p.y : ((t1i == h) ? rem : 0.0f);
    w0 *= sw.x; w1 *= sw.y;

    float ws = w0 + w1;
    #pragma unroll
    for (int o = 16; o; o >>= 1) ws += __shfl_xor_sync(FULL, ws, o);
    const float inv = 1.0f / fmaxf(ws, EPSILON);
    w0 *= inv; w1 *= inv;

    // weights + ponder outputs: one warp of one block per batch
    if (chunk == 0 && warp == 0) {
        reinterpret_cast<float2*>(out_weights + b * T_DIM)[lane] =
            make_float2(w0, w1);
        float pc = w0 * (float)(t0i + 1) + w1 * (float)(t1i + 1);
        #pragma unroll
        for (int o = 16; o; o >>= 1) pc += __shfl_xor_sync(FULL, pc, o);
        if (lane == 0) out_ponder[b] = pc;
    }

    // broadcast first-4 weights from lanes 0,1
    const float wa = __shfl_sync(FULL, w0, 0);   // t=0
    const float wb = __shfl_sync(FULL, w1, 0);   // t=1
    const float wc = __shfl_sync(FULL, w0, 1);   // t=2
    const float wd = __shfl_sync(FULL, w1, 1);   // t=3

    // ---- consume prefetched rows ----
    float4 accA, accB;
    accA.x = wa * a0.x; accA.y = wa * a0.y; accA.z = wa * a0.z; accA.w = wa * a0.w;
    accB.x = wa * b0.x; accB.y = wa * b0.y; accB.z = wa * b0.z; accB.w = wa * b0.w;

    accA.x = fmaf(wb, a1.x, accA.x); accA.y = fmaf(wb, a1.y, accA.y);
    accA.z = fmaf(wb, a1.z, accA.z); accA.w = fmaf(wb, a1.w, accA.w);
    accB.x = fmaf(wb, b1.x, accB.x); accB.y = fmaf(wb, b1.y, accB.y);
    accB.z = fmaf(wb, b1.z, accB.z); accB.w = fmaf(wb, b1.w, accB.w);

    accA.x = fmaf(wc, a2.x, accA.x); accA.y = fmaf(wc, a2.y, accA.y);
    accA.z = fmaf(wc, a2.z, accA.z); accA.w = fmaf(wc, a2.w, accA.w);
    accB.x = fmaf(wc, b2.x, accB.x); accB.y = fmaf(wc, b2.y, accB.y);
    accB.z = fmaf(wc, b2.z, accB.z); accB.w = fmaf(wc, b2.w, accB.w);

    accA.x = fmaf(wd, a3.x, accA.x); accA.y = fmaf(wd, a3.y, accA.y);
    accA.z = fmaf(wd, a3.z, accA.z); accA.w = fmaf(wd, a3.w, accA.w);
    accB.x = fmaf(wd, b3.x, accB.x); accB.y = fmaf(wd, b3.y, accB.y);
    accB.z = fmaf(wd, b3.z, accB.z); accB.w = fmaf(wd, b3.w, accB.w);

    // ---- rare tail: h >= PF (~4% of batches) ----
    for (int t0 = PF; t0 <= h; t0 += 2) {
        float4 ua[2], ub[2];
        #pragma unroll
        for (int i = 0; i < 2; i++) {
            const int t = t0 + i;
            if (t < T_DIM) {
                ua[i] = __ldcs(basea + (size_t)t * D4);
                ub[i] = __ldcs(baseb + (size_t)t * D4);
            } else {
                ua[i] = make_float4(0.f, 0.f, 0.f, 0.f);
                ub[i] = make_float4(0.f, 0.f, 0.f, 0.f);
            }
        }
        #pragma unroll
        for (int i = 0; i < 2; i++) {
            const int t = t0 + i;
            float wt = __shfl_sync(FULL, (t & 1) ? w1 : w0, (t >> 1) & 31);
            if (t >= T_DIM) wt = 0.0f;
            accA.x = fmaf(wt, ua[i].x, accA.x); accA.y = fmaf(wt, ua[i].y, accA.y);
            accA.z = fmaf(wt, ua[i].z, accA.z); accA.w = fmaf(wt, ua[i].w, accA.w);
            accB.x = fmaf(wt, ub[i].x, accB.x); accB.y = fmaf(wt, ub[i].y, accB.y);
            accB.z = fmaf(wt, ub[i].z, accB.z); accB.w = fmaf(wt, ub[i].w, accB.w);
        }
    }

    float4* fo = reinterpret_cast<float4*>(final_out) + (size_t)b * D4;
    fo[d4a] = accA;
    fo[d4b] = accB;
}

// ---------------------------------------------------------------------------
// kernel_launch
// Inputs: halt_probs [B,T,1], outputs [B,T,D], step_weights [B,T]  (fp32)
// Output: concat(final_output [B*D], ponder_cost [B], weights [B*T]) fp32
// ---------------------------------------------------------------------------
extern "C" void kernel_launch(void* const* d_in, const int* in_sizes, int n_in,
                              void* d_out, int out_size)
{
    const float* halt_probs   = (const float*)d_in[0];
    const float* outputs      = (const float*)d_in[1];
    const float* step_weights = (const float*)d_in[2];

    float* out         = (float*)d_out;
    float* final_out   = out;                              // [B,D]
    float* ponder_out  = out + (size_t)B_DIM * D_DIM;      // [B]
    float* weights_out = ponder_out + B_DIM;               // [B,T]

    act_sparse_kernel<<<B_DIM * BLOCKS_PER_B, THREADS>>>(
        halt_probs, outputs, step_weights,
        final_out, ponder_out, weights_out);
}